// round 15
// baseline (speedup 1.0000x reference)
#include <cuda_runtime.h>

// QSP expectation, single fused kernel, zero inter-block communication.
// Grid 128 x 1024 (one block per SM).
//
// g(theta) = Re(e^{i phi0} P00) = sum_{j<=27} A_j cos(2j th) + B_j sin(2j th)
//   (pi-periodic, band-limited 54). Per block:
//   1) threads 0-127: coefficient pipeline (setup -> split 27+27-step chain
//      -> P00 dot -> exact 64-pt DFT) under NAMED partial barriers.
//   2) 256-interval table: each 4-thread QUAD owns one interval; its lanes
//      compute the 4 stencil points g[j-1..j+2] (one scalar Clenshaw each),
//      exchange via __shfl_sync, lane 0 writes monomial cubic coeffs.
//      -> no g[] array, no extra phase, one fewer full barrier.
//   3) eval: range-reduce + one LDS.128 + 3-fma Horner, 4 elems/thread.

#define NSTEP 54
#define NHARM 27
#define NSAMP 64
#define TSIZE 256

__device__ __forceinline__ void bar128() {
    asm volatile("bar.sync 1, 128;" ::: "memory");
}

__global__ void __launch_bounds__(1024, 1)
qsp_fused(const float4* __restrict__ x4,
          const float*  __restrict__ phis,
          const float4* __restrict__ a4,
          const float*  __restrict__ bias,
          float4* __restrict__ out4,
          int nq)                       // nq = n/4
{
    __shared__ float pc[NSTEP], ps[NSTEP];
    __shared__ float s0cs[2];
    __shared__ float lh[64 * 4], rh[64 * 4];      // half-chain results
    __shared__ float gs[NSAMP];                   // g at 64 chain samples
    __shared__ float tab[NSAMP];                  // sinpi table for DFT
    __shared__ __align__(8)  float2 sAB[NHARM + 1];   // (A_k, B_k)
    __shared__ __align__(16) float4 cf[TSIZE];    // monomial cubic coeffs

    const int t = threadIdx.x;
    const int T = blockIdx.x * blockDim.x + t;
    const bool act = (T < nq);

    // ---- eval-path global loads issued FIRST ----
    float4 xv = make_float4(0.f, 0.f, 0.f, 0.f);
    float4 av = xv;
    if (act) { xv = x4[T]; av = a4[T]; }
    const float bb = bias[0];

    // ================= narrow pipeline: threads 0-127 only =================
    if (t < 128) {
        if (t < NSTEP) {
            float sp, cp; sincosf(phis[t + 1], &sp, &cp);   // accurate, one-time
            pc[t] = cp; ps[t] = sp;
        }
        if (t == 63) {
            float sp, cp; sincosf(phis[0], &sp, &cp);
            s0cs[0] = cp; s0cs[1] = sp;
        }
        if (t >= 64) {
            const int i = t - 64;
            tab[i] = sinpif((float)i * (1.0f / 32.0f));     // sin(pi*i/32)
        }
        bar128();

        // chain split: 0-63 left rows, 64-127 right cols (transposed)
        {
            const int i = t & 63;
            float s, c; sincospif((float)i * (1.0f / 64.0f), &s, &c);
            float x0, y0, x1, y1;
            if (t < 64) {
                x0 = 1.f; y0 = 0.f; x1 = 0.f; y1 = 0.f;
                #pragma unroll
                for (int k = 0; k < NHARM; ++k) {
                    const float ec = pc[k], es = ps[k];
                    const float ux = c * x0 - s * y1, uy = c * y0 + s * x1;
                    const float vx = c * x1 - s * y0, vy = c * y1 + s * x0;
                    x0 = ec * ux - es * uy; y0 = es * ux + ec * uy;
                    x1 = ec * vx + es * vy; y1 = ec * vy - es * vx;
                }
                lh[i*4+0] = x0; lh[i*4+1] = y0; lh[i*4+2] = x1; lh[i*4+3] = y1;
            } else {
                x0 = 1.f; y0 = 0.f; x1 = 0.f; y1 = 0.f;
                #pragma unroll
                for (int k = NSTEP - 1; k >= NHARM; --k) {
                    const float ec = pc[k], es = ps[k];
                    const float px = ec * x0 - es * y0, py = ec * y0 + es * x0;
                    const float qx = ec * x1 + es * y1, qy = ec * y1 - es * x1;
                    x0 = c * px - s * qy;  y0 = c * py + s * qx;
                    x1 = c * qx - s * py;  y1 = c * qy + s * px;
                }
                rh[i*4+0] = x0; rh[i*4+1] = y0; rh[i*4+2] = x1; rh[i*4+3] = y1;
            }
        }
        bar128();

        // P00 dot: g at the 64 chain samples
        if (t < 64) {
            const float r0x = lh[t*4], r0y = lh[t*4+1], r1x = lh[t*4+2], r1y = lh[t*4+3];
            const float v0x = rh[t*4], v0y = rh[t*4+1], v1x = rh[t*4+2], v1y = rh[t*4+3];
            const float Px = r0x*v0x - r0y*v0y + r1x*v1x - r1y*v1y;
            const float Py = r0x*v0y + r0y*v0x + r1x*v1y + r1y*v1x;
            gs[t] = s0cs[0] * Px - s0cs[1] * Py;
        }
        bar128();

        // exact 64-pt DFT, 8 accumulators: cos(pi*m/32)=tab[(m+16)&63]
        if (t <= NHARM) {
            float a[8] = {0,0,0,0,0,0,0,0};
            #pragma unroll
            for (int k = 0; k < NSAMP; k += 8) {
                #pragma unroll
                for (int j = 0; j < 8; ++j)
                    a[j] = fmaf(gs[k+j], tab[(t*(k+j) + 16) & 63], a[j]);
            }
            const float acc = ((a[0]+a[1]) + (a[2]+a[3])) + ((a[4]+a[5]) + (a[6]+a[7]));
            sAB[t].x = acc * ((t == 0) ? (1.0f / 64.0f) : (2.0f / 64.0f));
            if (t == 0) sAB[0].y = 0.0f;   // B_0 unused
        } else if (t >= 32 && t <= 31 + NHARM) {
            const int j = t - 31;
            float a[8] = {0,0,0,0,0,0,0,0};
            #pragma unroll
            for (int k = 0; k < NSAMP; k += 8) {
                #pragma unroll
                for (int m = 0; m < 8; ++m)
                    a[m] = fmaf(gs[k+m], tab[(j*(k+m)) & 63], a[m]);
            }
            sAB[j].y = (((a[0]+a[1]) + (a[2]+a[3])) + ((a[4]+a[5]) + (a[6]+a[7]))) * (2.0f / 64.0f);
        }
    }
    __syncthreads();   // sAB ready for the whole block

    // ---- table: quad (t>>2) owns interval j; lane (t&3) computes stencil
    //      point m = j + (t&3) - 1; quad-shuffle; lane 0 writes cf[j] ----
    {
        const int j = t >> 2;          // 0..255
        const int l = t & 3;           // lane in quad
        const int m = (j + l - 1) & (TSIZE - 1);   // periodic wrap

        // u = 2*theta_m = pi * m / 128
        float su, cu;
        sincospif((float)m * (1.0f / 128.0f), &su, &cu);
        const float tw = 2.0f * cu;

        float b1 = 0.f, b2 = 0.f, d1 = 0.f, d2 = 0.f;

        // 3-deep rolling prefetch (broadcast LDS.64); after loop f0 == sAB[0]
        float2 f0 = sAB[NHARM];
        float2 f1 = sAB[NHARM - 1];
        float2 f2 = sAB[NHARM - 2];

        #pragma unroll
        for (int k = NHARM; k >= 1; --k) {
            const float Ak = f0.x, Bk = f0.y;
            f0 = f1; f1 = f2;
            if (k >= 3) f2 = sAB[k - 3];
            float nb;
            nb = fmaf(tw, b1, Ak - b2); b2 = b1; b1 = nb;
            nb = fmaf(tw, d1, Bk - d2); d2 = d1; d1 = nb;
        }

        float gv = f0.x - b2;              // A0 - b2  (f0 == sAB[0])
        gv = fmaf(cu, b1, gv);
        gv = fmaf(su, d1, gv);

        // quad exchange (lanes of a quad are in the same warp)
        const int qb = t & 28;             // quad base lane within warp (t&31 & ~3)
        const float gm = __shfl_sync(0xffffffffu, gv, qb + 0, 32);
        const float g0 = __shfl_sync(0xffffffffu, gv, qb + 1, 32);
        const float gp = __shfl_sync(0xffffffffu, gv, qb + 2, 32);
        const float gq = __shfl_sync(0xffffffffu, gv, qb + 3, 32);

        if (l == 0) {
            const float c1 = gp - gm * (1.0f/3.0f) - g0 * 0.5f - gq * (1.0f/6.0f);
            const float c2 = 0.5f * (gm + gp) - g0;
            const float c3 = (3.0f * (g0 - gp) + gq - gm) * (1.0f/6.0f);
            cf[j] = make_float4(g0, c1, c2, c3);
        }
    }
    __syncthreads();

    // ---- evaluation: range-reduce + LDS.128 + 3-fma Horner ----
    if (!act) return;

    const float SCALE = (float)TSIZE / 3.14159265358979323846f;
    float th[4] = {xv.x, xv.y, xv.z, xv.w};
    float res[4];
    #pragma unroll
    for (int e = 0; e < 4; ++e) {
        const float u  = th[e] * SCALE;
        const float fl = floorf(u);
        const float f  = u - fl;
        const int idx  = ((int)fl) & (TSIZE - 1);
        const float4 c = cf[idx];
        res[e] = fmaf(fmaf(fmaf(c.w, f, c.z), f, c.y), f, c.x);
    }

    out4[T] = make_float4(fmaf(av.x, res[0], bb), fmaf(av.y, res[1], bb),
                          fmaf(av.z, res[2], bb), fmaf(av.w, res[3], bb));
}

// ---------------------------------------------------------------------------
// Fallback for unexpected shapes (direct chain evaluation).
// ---------------------------------------------------------------------------
__global__ void __launch_bounds__(256)
qsp_generic(const float* __restrict__ x,
            const float* __restrict__ phis,
            const float* __restrict__ alphas,
            const float* __restrict__ bias,
            float* __restrict__ out,
            int n, int nsteps)
{
    __shared__ float pc[256], ps[256];
    __shared__ float s0c, s0s;
    int t = threadIdx.x;
    if (t < nsteps && t < 256) {
        float sp, cp; sincosf(phis[t + 1], &sp, &cp);
        pc[t] = cp; ps[t] = sp;
    }
    if (t == 0) {
        float sp, cp; sincosf(phis[0], &sp, &cp);
        s0c = cp; s0s = sp;
    }
    __syncthreads();

    const int i = blockIdx.x * blockDim.x + t;
    if (i >= n) return;

    float s, c; sincosf(x[i], &s, &c);
    float x0 = 1.0f, y0 = 0.0f, x1 = 0.0f, y1 = 0.0f;
    for (int k = 0; k < nsteps; ++k) {
        const float ec = (k < 256) ? pc[k] : cosf(phis[k + 1]);
        const float es = (k < 256) ? ps[k] : sinf(phis[k + 1]);
        const float ux = c * x0 - s * y1;
        const float uy = c * y0 + s * x1;
        const float vx = c * x1 - s * y0;
        const float vy = c * y1 + s * x0;
        x0 = ec * ux - es * uy;
        y0 = es * ux + ec * uy;
        x1 = ec * vx + es * vy;
        y1 = ec * vy - es * vx;
    }
    const float re = s0c * x0 - s0s * y0;
    out[i] = fmaf(alphas[i], re, bias[0]);
}

extern "C" void kernel_launch(void* const* d_in, const int* in_sizes, int n_in,
                              void* d_out, int out_size)
{
    const float* x      = (const float*)d_in[0];
    const float* phis   = (const float*)d_in[1];
    const float* alphas = (const float*)d_in[2];
    const float* bias   = (const float*)d_in[3];
    float* out = (float*)d_out;

    const int n      = in_sizes[0];
    const int nph    = in_sizes[1];
    const int nsteps = nph - 1;

    if (nsteps == NSTEP && (n & 3) == 0) {
        const int nq      = n >> 2;                   // float4 quads
        const int threads = 1024;
        const int blocks  = (nq + threads - 1) / threads;   // 128 for n=524288
        qsp_fused<<<blocks, threads>>>((const float4*)x, phis,
                                       (const float4*)alphas, bias,
                                       (float4*)out, nq);
    } else {
        const int threads = 256;
        const int blocks  = (n + threads - 1) / threads;
        qsp_generic<<<blocks, threads>>>(x, phis, alphas, bias, out, n, nsteps);
    }
}

// round 16
// speedup vs baseline: 1.0295x; 1.0295x over previous
#include <cuda_runtime.h>

// QSP expectation, single fused kernel, zero inter-block communication.
// Grid 128 x 1024 (one block per SM). ONE full-block barrier total.
//
// g(theta) = Re(e^{i phi0} P00) = sum_{j<=27} A_j cos(2j th) + B_j sin(2j th)
//   (pi-periodic, band-limited 54). Per block:
//   1) threads 0-127: coefficient pipeline (setup -> split 27+27-step chain
//      -> P00 dot -> exact 64-pt DFT) under bar.sync 1,128.
//   2) threads 0-255: 256-entry table of g (one scalar Clenshaw each) and
//      monomial cubic coeffs, under bar.sync 2,256.
//   3) single __syncthreads, then eval: range-reduce + one LDS.128 +
//      3-fma Horner, 4 elements/thread, early LDGs.

#define NSTEP 54
#define NHARM 27
#define NSAMP 64
#define TSIZE 256

__device__ __forceinline__ void bar128() {
    asm volatile("bar.sync 1, 128;" ::: "memory");
}
__device__ __forceinline__ void bar256() {
    asm volatile("bar.sync 2, 256;" ::: "memory");
}

__global__ void __launch_bounds__(1024, 1)
qsp_fused(const float4* __restrict__ x4,
          const float*  __restrict__ phis,
          const float4* __restrict__ a4,
          const float*  __restrict__ bias,
          float4* __restrict__ out4,
          int nq)                       // nq = n/4
{
    __shared__ float pc[NSTEP], ps[NSTEP];
    __shared__ float s0cs[2];
    __shared__ float lh[64 * 4], rh[64 * 4];      // half-chain results
    __shared__ float gs[NSAMP];                   // g at 64 chain samples
    __shared__ float tab[NSAMP];                  // sinpi table for DFT
    __shared__ __align__(8)  float2 sAB[NHARM + 1];   // (A_k, B_k)
    __shared__ __align__(16) float  g[TSIZE];     // g over one period
    __shared__ __align__(16) float4 cf[TSIZE];    // monomial cubic coeffs

    const int t = threadIdx.x;
    const int T = blockIdx.x * blockDim.x + t;
    const bool act = (T < nq);

    // ---- eval-path global loads issued FIRST ----
    float4 xv = make_float4(0.f, 0.f, 0.f, 0.f);
    float4 av = xv;
    if (act) { xv = x4[T]; av = a4[T]; }
    const float bb = bias[0];

    // ============ narrow pipeline + table: threads 0-255 only ============
    if (t < 256) {
        if (t < 128) {
            // ---- setup (threads 0-127) ----
            if (t < NSTEP) {
                float sp, cp; sincosf(phis[t + 1], &sp, &cp);   // accurate
                pc[t] = cp; ps[t] = sp;
            }
            if (t == 63) {
                float sp, cp; sincosf(phis[0], &sp, &cp);
                s0cs[0] = cp; s0cs[1] = sp;
            }
            if (t >= 64) {
                const int i = t - 64;
                tab[i] = sinpif((float)i * (1.0f / 32.0f));     // sin(pi*i/32)
            }
            bar128();

            // ---- chain split: 0-63 left rows, 64-127 right cols ----
            {
                const int i = t & 63;
                float s, c; sincospif((float)i * (1.0f / 64.0f), &s, &c);
                float x0, y0, x1, y1;
                if (t < 64) {
                    x0 = 1.f; y0 = 0.f; x1 = 0.f; y1 = 0.f;
                    #pragma unroll
                    for (int k = 0; k < NHARM; ++k) {
                        const float ec = pc[k], es = ps[k];
                        const float ux = c * x0 - s * y1, uy = c * y0 + s * x1;
                        const float vx = c * x1 - s * y0, vy = c * y1 + s * x0;
                        x0 = ec * ux - es * uy; y0 = es * ux + ec * uy;
                        x1 = ec * vx + es * vy; y1 = ec * vy - es * vx;
                    }
                    lh[i*4+0] = x0; lh[i*4+1] = y0; lh[i*4+2] = x1; lh[i*4+3] = y1;
                } else {
                    x0 = 1.f; y0 = 0.f; x1 = 0.f; y1 = 0.f;
                    #pragma unroll
                    for (int k = NSTEP - 1; k >= NHARM; --k) {
                        const float ec = pc[k], es = ps[k];
                        const float px = ec * x0 - es * y0, py = ec * y0 + es * x0;
                        const float qx = ec * x1 + es * y1, qy = ec * y1 - es * x1;
                        x0 = c * px - s * qy;  y0 = c * py + s * qx;
                        x1 = c * qx - s * py;  y1 = c * qy + s * px;
                    }
                    rh[i*4+0] = x0; rh[i*4+1] = y0; rh[i*4+2] = x1; rh[i*4+3] = y1;
                }
            }
            bar128();

            // ---- P00 dot: g at the 64 chain samples ----
            if (t < 64) {
                const float r0x = lh[t*4], r0y = lh[t*4+1], r1x = lh[t*4+2], r1y = lh[t*4+3];
                const float v0x = rh[t*4], v0y = rh[t*4+1], v1x = rh[t*4+2], v1y = rh[t*4+3];
                const float Px = r0x*v0x - r0y*v0y + r1x*v1x - r1y*v1y;
                const float Py = r0x*v0y + r0y*v0x + r1x*v1y + r1y*v1x;
                gs[t] = s0cs[0] * Px - s0cs[1] * Py;
            }
            bar128();

            // ---- exact 64-pt DFT, 8 accumulators ----
            if (t <= NHARM) {
                float a[8] = {0,0,0,0,0,0,0,0};
                #pragma unroll
                for (int k = 0; k < NSAMP; k += 8) {
                    #pragma unroll
                    for (int j = 0; j < 8; ++j)
                        a[j] = fmaf(gs[k+j], tab[(t*(k+j) + 16) & 63], a[j]);
                }
                const float acc = ((a[0]+a[1]) + (a[2]+a[3])) + ((a[4]+a[5]) + (a[6]+a[7]));
                sAB[t].x = acc * ((t == 0) ? (1.0f / 64.0f) : (2.0f / 64.0f));
                if (t == 0) sAB[0].y = 0.0f;   // B_0 unused
            } else if (t >= 32 && t <= 31 + NHARM) {
                const int j = t - 31;
                float a[8] = {0,0,0,0,0,0,0,0};
                #pragma unroll
                for (int k = 0; k < NSAMP; k += 8) {
                    #pragma unroll
                    for (int m = 0; m < 8; ++m)
                        a[m] = fmaf(gs[k+m], tab[(j*(k+m)) & 63], a[m]);
                }
                sAB[j].y = (((a[0]+a[1]) + (a[2]+a[3])) + ((a[4]+a[5]) + (a[6]+a[7]))) * (2.0f / 64.0f);
            }
        }
        bar256();   // sAB ready for threads 0-255

        // ---- table build: threads 0-255, one grid point each ----
        {
            // u = 2*theta_t = pi * t / 128
            float su, cu;
            sincospif((float)t * (1.0f / 128.0f), &su, &cu);
            const float tw = 2.0f * cu;

            float b1 = 0.f, b2 = 0.f, d1 = 0.f, d2 = 0.f;

            // 3-deep rolling prefetch (broadcast LDS.64); after loop f0 == sAB[0]
            float2 f0 = sAB[NHARM];
            float2 f1 = sAB[NHARM - 1];
            float2 f2 = sAB[NHARM - 2];

            #pragma unroll
            for (int k = NHARM; k >= 1; --k) {
                const float Ak = f0.x, Bk = f0.y;
                f0 = f1; f1 = f2;
                if (k >= 3) f2 = sAB[k - 3];

                float nb;
                nb = fmaf(tw, b1, Ak - b2); b2 = b1; b1 = nb;
                nb = fmaf(tw, d1, Bk - d2); d2 = d1; d1 = nb;
            }

            float gv = f0.x - b2;              // A0 - b2  (f0 == sAB[0])
            gv = fmaf(cu, b1, gv);
            gv = fmaf(su, d1, gv);
            g[t] = gv;
        }
        bar256();

        // ---- monomial cubic coefficients per interval (threads 0-255) ----
        {
            const float gm = g[(t + TSIZE - 1) & (TSIZE - 1)];
            const float g0 = g[t];
            const float gp = g[(t + 1) & (TSIZE - 1)];
            const float gq = g[(t + 2) & (TSIZE - 1)];
            const float c1 = gp - gm * (1.0f/3.0f) - g0 * 0.5f - gq * (1.0f/6.0f);
            const float c2 = 0.5f * (gm + gp) - g0;
            const float c3 = (3.0f * (g0 - gp) + gq - gm) * (1.0f/6.0f);
            cf[t] = make_float4(g0, c1, c2, c3);
        }
    }
    __syncthreads();   // the ONLY full-block barrier

    // ---- evaluation: range-reduce + LDS.128 + 3-fma Horner ----
    if (!act) return;

    const float SCALE = (float)TSIZE / 3.14159265358979323846f;
    float th[4] = {xv.x, xv.y, xv.z, xv.w};
    float res[4];
    #pragma unroll
    for (int e = 0; e < 4; ++e) {
        const float u  = th[e] * SCALE;
        const float fl = floorf(u);
        const float f  = u - fl;
        const int idx  = ((int)fl) & (TSIZE - 1);
        const float4 c = cf[idx];
        res[e] = fmaf(fmaf(fmaf(c.w, f, c.z), f, c.y), f, c.x);
    }

    out4[T] = make_float4(fmaf(av.x, res[0], bb), fmaf(av.y, res[1], bb),
                          fmaf(av.z, res[2], bb), fmaf(av.w, res[3], bb));
}

// ---------------------------------------------------------------------------
// Fallback for unexpected shapes (direct chain evaluation).
// ---------------------------------------------------------------------------
__global__ void __launch_bounds__(256)
qsp_generic(const float* __restrict__ x,
            const float* __restrict__ phis,
            const float* __restrict__ alphas,
            const float* __restrict__ bias,
            float* __restrict__ out,
            int n, int nsteps)
{
    __shared__ float pc[256], ps[256];
    __shared__ float s0c, s0s;
    int t = threadIdx.x;
    if (t < nsteps && t < 256) {
        float sp, cp; sincosf(phis[t + 1], &sp, &cp);
        pc[t] = cp; ps[t] = sp;
    }
    if (t == 0) {
        float sp, cp; sincosf(phis[0], &sp, &cp);
        s0c = cp; s0s = sp;
    }
    __syncthreads();

    const int i = blockIdx.x * blockDim.x + t;
    if (i >= n) return;

    float s, c; sincosf(x[i], &s, &c);
    float x0 = 1.0f, y0 = 0.0f, x1 = 0.0f, y1 = 0.0f;
    for (int k = 0; k < nsteps; ++k) {
        const float ec = (k < 256) ? pc[k] : cosf(phis[k + 1]);
        const float es = (k < 256) ? ps[k] : sinf(phis[k + 1]);
        const float ux = c * x0 - s * y1;
        const float uy = c * y0 + s * x1;
        const float vx = c * x1 - s * y0;
        const float vy = c * y1 + s * x0;
        x0 = ec * ux - es * uy;
        y0 = es * ux + ec * uy;
        x1 = ec * vx + es * vy;
        y1 = ec * vy - es * vx;
    }
    const float re = s0c * x0 - s0s * y0;
    out[i] = fmaf(alphas[i], re, bias[0]);
}

extern "C" void kernel_launch(void* const* d_in, const int* in_sizes, int n_in,
                              void* d_out, int out_size)
{
    const float* x      = (const float*)d_in[0];
    const float* phis   = (const float*)d_in[1];
    const float* alphas = (const float*)d_in[2];
    const float* bias   = (const float*)d_in[3];
    float* out = (float*)d_out;

    const int n      = in_sizes[0];
    const int nph    = in_sizes[1];
    const int nsteps = nph - 1;

    if (nsteps == NSTEP && (n & 3) == 0) {
        const int nq      = n >> 2;                   // float4 quads
        const int threads = 1024;
        const int blocks  = (nq + threads - 1) / threads;   // 128 for n=524288
        qsp_fused<<<blocks, threads>>>((const float4*)x, phis,
                                       (const float4*)alphas, bias,
                                       (float4*)out, nq);
    } else {
        const int threads = 256;
        const int blocks  = (n + threads - 1) / threads;
        qsp_generic<<<blocks, threads>>>(x, phis, alphas, bias, out, n, nsteps);
    }
}